// round 1
// baseline (speedup 1.0000x reference)
#include <cuda_runtime.h>
#include <cuda_bf16.h>
#include <cstddef>

// Problem constants
#define NB   2          // batch
#define LSEQ 2048       // sequence length
#define DIM  1024       // model dim
#define NH   16         // heads
#define DH   64         // per-head dim
#define CHK  128        // chunk length for linear attention
#define NCHK (LSEQ / CHK)   // 16 chunks
#define MROWS (NB * LSEQ)   // 4096

// Scratch (device globals; no allocation allowed)
__device__ float g_Q[MROWS * DIM];                 // softmaxed projected Q
__device__ float g_K[MROWS * DIM];                 // softmaxed projected K
__device__ float g_V[MROWS * DIM];                 // projected V
__device__ float g_P[NB * NH * NCHK * DH * DH];    // per-chunk KV sums -> exclusive prefixes

// ---------------------------------------------------------------------------
// SGEMM (NT): Out[m,n] = sum_k X[m,k] * W[n,k].  M=4096, N=K=1024.
// BM=BN=128, BK=16, 256 threads, 8x8 per thread.
// sel picks the destination scratch buffer.
// ---------------------------------------------------------------------------
__global__ __launch_bounds__(256, 2)
void sgemm_nt(const float* __restrict__ X, const float* __restrict__ W, int sel)
{
    float* Out = (sel == 0) ? g_Q : (sel == 1) ? g_K : g_V;

    __shared__ float As[16][128];
    __shared__ float Bs[16][128];

    const int m0 = blockIdx.y * 128;
    const int n0 = blockIdx.x * 128;
    const int tid = threadIdx.x;
    const int tx = tid & 15;      // 0..15  -> 8 cols each
    const int ty = tid >> 4;      // 0..15  -> 8 rows each

    float acc[8][8];
#pragma unroll
    for (int i = 0; i < 8; i++)
#pragma unroll
        for (int j = 0; j < 8; j++) acc[i][j] = 0.f;

    for (int k0 = 0; k0 < DIM; k0 += 16) {
        // load X tile (128 rows x 16 k) -> As[k][m] transposed
#pragma unroll
        for (int it = 0; it < 2; it++) {
            int idx = tid + it * 256;          // 0..511 float4 slots
            int row = idx >> 2;
            int kq  = idx & 3;
            float4 f = *(const float4*)&X[(size_t)(m0 + row) * DIM + k0 + kq * 4];
            As[kq * 4 + 0][row] = f.x;
            As[kq * 4 + 1][row] = f.y;
            As[kq * 4 + 2][row] = f.z;
            As[kq * 4 + 3][row] = f.w;
        }
#pragma unroll
        for (int it = 0; it < 2; it++) {
            int idx = tid + it * 256;
            int row = idx >> 2;
            int kq  = idx & 3;
            float4 f = *(const float4*)&W[(size_t)(n0 + row) * DIM + k0 + kq * 4];
            Bs[kq * 4 + 0][row] = f.x;
            Bs[kq * 4 + 1][row] = f.y;
            Bs[kq * 4 + 2][row] = f.z;
            Bs[kq * 4 + 3][row] = f.w;
        }
        __syncthreads();

#pragma unroll
        for (int kk = 0; kk < 16; kk++) {
            float a[8], b[8];
#pragma unroll
            for (int i = 0; i < 8; i++) a[i] = As[kk][ty * 8 + i];
#pragma unroll
            for (int j = 0; j < 8; j++) b[j] = Bs[kk][tx * 8 + j];
#pragma unroll
            for (int i = 0; i < 8; i++)
#pragma unroll
                for (int j = 0; j < 8; j++)
                    acc[i][j] = fmaf(a[i], b[j], acc[i][j]);
        }
        __syncthreads();
    }

#pragma unroll
    for (int i = 0; i < 8; i++) {
        int m = m0 + ty * 8 + i;
#pragma unroll
        for (int j = 0; j < 8; j += 4) {
            float4 f = make_float4(acc[i][j], acc[i][j + 1], acc[i][j + 2], acc[i][j + 3]);
            *(float4*)&Out[(size_t)m * DIM + n0 + tx * 8 + j] = f;
        }
    }
}

// ---------------------------------------------------------------------------
// softmax over contiguous segments of 64 (per (n,l,h)); one warp per segment.
// ---------------------------------------------------------------------------
__global__ __launch_bounds__(256)
void softmax64(int sel)
{
    float* buf = (sel == 0) ? g_Q : g_K;
    int seg = blockIdx.x * 8 + (threadIdx.x >> 5);
    int lane = threadIdx.x & 31;
    float* p = buf + (size_t)seg * 64;

    float v0 = p[lane];
    float v1 = p[lane + 32];
    float m = fmaxf(v0, v1);
#pragma unroll
    for (int o = 16; o > 0; o >>= 1) m = fmaxf(m, __shfl_xor_sync(0xffffffffu, m, o));
    float e0 = __expf(v0 - m);
    float e1 = __expf(v1 - m);
    float s = e0 + e1;
#pragma unroll
    for (int o = 16; o > 0; o >>= 1) s += __shfl_xor_sync(0xffffffffu, s, o);
    float inv = 1.0f / s;
    p[lane]      = e0 * inv;
    p[lane + 32] = e1 * inv;
}

// ---------------------------------------------------------------------------
// Per-chunk KV outer-product sums: P[n,h,c] = sum_{t in chunk} k_t^T v_t (64x64)
// grid: (NCHK, NB*NH), 256 threads, dynamic smem 64KB.
// ---------------------------------------------------------------------------
__global__ __launch_bounds__(256)
void chunk_kv()
{
    extern __shared__ float sm[];
    float* ks = sm;          // 128*64
    float* vs = sm + 8192;   // 128*64

    const int c  = blockIdx.x;
    const int nh = blockIdx.y;
    const int n = nh >> 4, h = nh & 15;
    const int t0 = c * CHK;
    const size_t base = ((size_t)(n * LSEQ + t0)) * DIM + h * DH;

    for (int idx = threadIdx.x; idx < CHK * DH; idx += 256) {
        int row = idx >> 6, col = idx & 63;
        ks[idx] = g_K[base + (size_t)row * DIM + col];
        vs[idx] = g_V[base + (size_t)row * DIM + col];
    }
    __syncthreads();

    const int tx = threadIdx.x & 15;   // -> 4 cols
    const int ty = threadIdx.x >> 4;   // -> 4 rows
    float acc[4][4];
#pragma unroll
    for (int i = 0; i < 4; i++)
#pragma unroll
        for (int j = 0; j < 4; j++) acc[i][j] = 0.f;

    for (int t = 0; t < CHK; t++) {
        float a[4], b[4];
#pragma unroll
        for (int i = 0; i < 4; i++) a[i] = ks[t * 64 + ty * 4 + i];
#pragma unroll
        for (int j = 0; j < 4; j++) b[j] = vs[t * 64 + tx * 4 + j];
#pragma unroll
        for (int i = 0; i < 4; i++)
#pragma unroll
            for (int j = 0; j < 4; j++)
                acc[i][j] = fmaf(a[i], b[j], acc[i][j]);
    }

    float* P = g_P + ((size_t)nh * NCHK + c) * (DH * DH);
#pragma unroll
    for (int i = 0; i < 4; i++)
#pragma unroll
        for (int j = 0; j < 4; j++)
            P[(ty * 4 + i) * 64 + tx * 4 + j] = acc[i][j];
}

// ---------------------------------------------------------------------------
// Exclusive prefix over chunks (in place): P[c] <- sum_{c'<c} P[c'].
// grid: NB*NH blocks, 512 threads, 8 elems each.
// ---------------------------------------------------------------------------
__global__ __launch_bounds__(512)
void prefix_kv()
{
    float* P = g_P + (size_t)blockIdx.x * NCHK * (DH * DH);
    int e = threadIdx.x;
#pragma unroll
    for (int j = 0; j < 8; j++) {
        int idx = e + j * 512;
        float run = 0.f;
        for (int c = 0; c < NCHK; c++) {
            float t = P[c * (DH * DH) + idx];
            P[c * (DH * DH) + idx] = run;
            run += t;
        }
    }
}

// ---------------------------------------------------------------------------
// Output: out_chunk = causal(q k^T) v + q @ S_excl
// grid: (NCHK, NB*NH), 256 threads, dynamic smem 144KB.
// ---------------------------------------------------------------------------
__global__ __launch_bounds__(256)
void attn_out(float* __restrict__ out)
{
    extern __shared__ float sm[];
    float* qs = sm;            // 128*64 = 8192
    float* Am = sm + 8192;     // 128*128 = 16384
    float* R2 = sm + 24576;    // stage1: kT (64*128=8192); stage2: vs(8192)+Ss(4096)

    const int c  = blockIdx.x;
    const int nh = blockIdx.y;
    const int n = nh >> 4, h = nh & 15;
    const int t0 = c * CHK;
    const size_t base = ((size_t)(n * LSEQ + t0)) * DIM + h * DH;
    const int tid = threadIdx.x;
    const int tx = tid & 15;
    const int ty = tid >> 4;

    // load q (row-major) and k transposed (kT[d][s]) for conflict-free A compute
    float* kT = R2;
    for (int idx = tid; idx < CHK * DH; idx += 256) {
        int row = idx >> 6, col = idx & 63;
        float qv = g_Q[base + (size_t)row * DIM + col];
        float kv = g_K[base + (size_t)row * DIM + col];
        qs[idx] = qv;
        kT[col * CHK + row] = kv;
    }
    __syncthreads();

    // Stage 1: A = causal(q @ k^T), 8x8 per thread over 128x128
    {
        float acc[8][8];
#pragma unroll
        for (int i = 0; i < 8; i++)
#pragma unroll
            for (int j = 0; j < 8; j++) acc[i][j] = 0.f;

        for (int d = 0; d < DH; d++) {
            float a[8], b[8];
#pragma unroll
            for (int i = 0; i < 8; i++) a[i] = qs[(ty * 8 + i) * 64 + d];
#pragma unroll
            for (int j = 0; j < 8; j++) b[j] = kT[d * CHK + tx * 8 + j];
#pragma unroll
            for (int i = 0; i < 8; i++)
#pragma unroll
                for (int j = 0; j < 8; j++)
                    acc[i][j] = fmaf(a[i], b[j], acc[i][j]);
        }
#pragma unroll
        for (int i = 0; i < 8; i++) {
            int r = ty * 8 + i;
#pragma unroll
            for (int j = 0; j < 8; j++) {
                int s = tx * 8 + j;
                Am[r * CHK + s] = (s <= r) ? acc[i][j] : 0.f;
            }
        }
    }
    __syncthreads();

    // Stage 2: load v and S_excl (reuse R2)
    float* vs = R2;
    float* Ss = R2 + 8192;
    for (int idx = tid; idx < CHK * DH; idx += 256) {
        int row = idx >> 6, col = idx & 63;
        vs[idx] = g_V[base + (size_t)row * DIM + col];
    }
    {
        const float* Pp = g_P + ((size_t)nh * NCHK + c) * (DH * DH);
        for (int idx = tid; idx < DH * DH; idx += 256) Ss[idx] = Pp[idx];
    }
    __syncthreads();

    // out[r][col] = sum_d q[r][d]*S[d][col] + sum_s A[r][s]*v[s][col]
    float o[8][4];
#pragma unroll
    for (int i = 0; i < 8; i++)
#pragma unroll
        for (int j = 0; j < 4; j++) o[i][j] = 0.f;

    for (int d = 0; d < DH; d++) {
        float a[8], b[4];
#pragma unroll
        for (int i = 0; i < 8; i++) a[i] = qs[(ty * 8 + i) * 64 + d];
#pragma unroll
        for (int j = 0; j < 4; j++) b[j] = Ss[d * 64 + tx * 4 + j];
#pragma unroll
        for (int i = 0; i < 8; i++)
#pragma unroll
            for (int j = 0; j < 4; j++)
                o[i][j] = fmaf(a[i], b[j], o[i][j]);
    }
    for (int s = 0; s < CHK; s++) {
        float a[8], b[4];
#pragma unroll
        for (int i = 0; i < 8; i++) a[i] = Am[(ty * 8 + i) * CHK + s];
#pragma unroll
        for (int j = 0; j < 4; j++) b[j] = vs[s * 64 + tx * 4 + j];
#pragma unroll
        for (int i = 0; i < 8; i++)
#pragma unroll
            for (int j = 0; j < 4; j++)
                o[i][j] = fmaf(a[i], b[j], o[i][j]);
    }

#pragma unroll
    for (int i = 0; i < 8; i++) {
        int r = ty * 8 + i;
#pragma unroll
        for (int j = 0; j < 4; j++)
            out[base + (size_t)r * DIM + tx * 4 + j] = o[i][j];
    }
}

// ---------------------------------------------------------------------------
extern "C" void kernel_launch(void* const* d_in, const int* in_sizes, int n_in,
                              void* d_out, int out_size)
{
    const float* query = (const float*)d_in[0];
    const float* key   = (const float*)d_in[1];
    const float* Wq    = (const float*)d_in[2];
    const float* Wk    = (const float*)d_in[3];
    const float* Wv    = (const float*)d_in[4];
    float* out = (float*)d_out;

    // opt-in dynamic smem (idempotent; host-side, not captured as graph nodes)
    cudaFuncSetAttribute(chunk_kv, cudaFuncAttributeMaxDynamicSharedMemorySize, 65536);
    cudaFuncSetAttribute(attn_out, cudaFuncAttributeMaxDynamicSharedMemorySize, 147456);

    dim3 ggrid(DIM / 128, MROWS / 128);   // (8, 32)
    sgemm_nt<<<ggrid, 256>>>(query, Wq, 0);
    sgemm_nt<<<ggrid, 256>>>(key,   Wk, 1);
    sgemm_nt<<<ggrid, 256>>>(key,   Wv, 2);

    // softmax over 64-wide head segments of Q and K
    int nseg = MROWS * NH;                // 65536
    softmax64<<<nseg / 8, 256>>>(0);
    softmax64<<<nseg / 8, 256>>>(1);

    dim3 agrid(NCHK, NB * NH);            // (16, 32)
    chunk_kv<<<agrid, 256, 65536>>>();
    prefix_kv<<<NB * NH, 512>>>();
    attn_out<<<agrid, 256, 147456>>>(out);
}

// round 4
// speedup vs baseline: 1.7098x; 1.7098x over previous
#include <cuda_runtime.h>
#include <cuda_bf16.h>
#include <cstdint>
#include <cstddef>

// ---------------- problem constants ----------------
#define NBATCH 2
#define LSEQ   2048
#define DIM    1024
#define NH     16
#define DH     64
#define CHK    128
#define NCHK   (LSEQ / CHK)      // 16
#define MROWS  (NBATCH * LSEQ)   // 4096

// ---------------- device scratch (no allocs allowed) ----------------
__device__ __align__(16) float g_Q[MROWS * DIM];
__device__ __align__(16) float g_K[MROWS * DIM];
__device__ __align__(16) float g_V[MROWS * DIM];
__device__ __align__(16) float g_P[NBATCH * NH * NCHK * DH * DH];
__device__ __align__(16) __nv_bfloat16 g_Xhi[2][MROWS * DIM];   // 0=query 1=key
__device__ __align__(16) __nv_bfloat16 g_Xlo[2][MROWS * DIM];
__device__ __align__(16) __nv_bfloat16 g_Whi[3][DIM * DIM];     // Wq,Wk,Wv
__device__ __align__(16) __nv_bfloat16 g_Wlo[3][DIM * DIM];

// ---------------- small helpers ----------------
__device__ __forceinline__ uint32_t smem_u32(const void* p) {
    uint32_t a;
    asm("{ .reg .u64 t; cvta.to.shared.u64 t, %1; cvt.u32.u64 %0, t; }" : "=r"(a) : "l"(p));
    return a;
}
__device__ __forceinline__ void cp16(uint32_t s, const void* g) {
    asm volatile("cp.async.cg.shared.global [%0], [%1], 16;" :: "r"(s), "l"(g));
}
#define CP_COMMIT() asm volatile("cp.async.commit_group;" ::: "memory")
#define CP_WAIT1()  asm volatile("cp.async.wait_group 1;" ::: "memory")
#define CP_WAIT0()  asm volatile("cp.async.wait_group 0;" ::: "memory")

__device__ __forceinline__ void mma16816(float* c, const uint32_t* a, const uint32_t* b) {
    asm volatile(
        "mma.sync.aligned.m16n8k16.row.col.f32.bf16.bf16.f32 "
        "{%0,%1,%2,%3}, {%4,%5,%6,%7}, {%8,%9}, {%0,%1,%2,%3};"
        : "+f"(c[0]), "+f"(c[1]), "+f"(c[2]), "+f"(c[3])
        : "r"(a[0]), "r"(a[1]), "r"(a[2]), "r"(a[3]), "r"(b[0]), "r"(b[1]));
}

// ---------------- bf16 hi/lo split conversion ----------------
__global__ __launch_bounds__(256)
void conv_split(const float* __restrict__ q, const float* __restrict__ k,
                const float* __restrict__ wq, const float* __restrict__ wk,
                const float* __restrict__ wv)
{
    int y = blockIdx.y;
    const float* src;
    __nv_bfloat16 *hi, *lo;
    int n;
    switch (y) {
        case 0: src = q;  hi = g_Xhi[0]; lo = g_Xlo[0]; n = MROWS * DIM; break;
        case 1: src = k;  hi = g_Xhi[1]; lo = g_Xlo[1]; n = MROWS * DIM; break;
        case 2: src = wq; hi = g_Whi[0]; lo = g_Wlo[0]; n = DIM * DIM;   break;
        case 3: src = wk; hi = g_Whi[1]; lo = g_Wlo[1]; n = DIM * DIM;   break;
        default: src = wv; hi = g_Whi[2]; lo = g_Wlo[2]; n = DIM * DIM;  break;
    }
    int n4 = n >> 2;
    for (int i = blockIdx.x * blockDim.x + threadIdx.x; i < n4;
         i += gridDim.x * blockDim.x) {
        float4 f = ((const float4*)src)[i];
        __nv_bfloat16 h0 = __float2bfloat16(f.x);
        __nv_bfloat16 h1 = __float2bfloat16(f.y);
        __nv_bfloat16 h2 = __float2bfloat16(f.z);
        __nv_bfloat16 h3 = __float2bfloat16(f.w);
        __nv_bfloat16 l0 = __float2bfloat16(f.x - __bfloat162float(h0));
        __nv_bfloat16 l1 = __float2bfloat16(f.y - __bfloat162float(h1));
        __nv_bfloat16 l2 = __float2bfloat16(f.z - __bfloat162float(h2));
        __nv_bfloat16 l3 = __float2bfloat16(f.w - __bfloat162float(h3));
        ushort4 uh = make_ushort4(__bfloat16_as_ushort(h0), __bfloat16_as_ushort(h1),
                                  __bfloat16_as_ushort(h2), __bfloat16_as_ushort(h3));
        ushort4 ul = make_ushort4(__bfloat16_as_ushort(l0), __bfloat16_as_ushort(l1),
                                  __bfloat16_as_ushort(l2), __bfloat16_as_ushort(l3));
        ((ushort4*)hi)[i] = uh;
        ((ushort4*)lo)[i] = ul;
    }
}

// ---------------- HMMA projection GEMM ----------------
// Out[m,n] = sum_k X[m,k]*W[n,k], computed as Ahi*Bhi + Ahi*Blo + Alo*Bhi.
// 128x128 CTA tile, BK=32 (96 k-iters = 3 passes x 32), 8 warps of 64x32,
// m16n8k16 bf16 mma, 2-stage cp.async pipeline, pitch-80B smem (conflict-free).
#define PITCH 40            // halves per row (80 bytes)
#define STG_B (128 * 80)    // 10240 bytes per stage per operand

__global__ __launch_bounds__(256, 2)
void proj_hmma()
{
    __shared__ __align__(16) __nv_bfloat16 smA[2][128][PITCH];
    __shared__ __align__(16) __nv_bfloat16 smB[2][128][PITCH];

    const int tid = threadIdx.x;
    const int wid = tid >> 5;
    const int lane = tid & 31;
    const int g = lane >> 2;       // group 0..7
    const int tg = lane & 3;       // 0..3
    const int wm = wid >> 2;       // 0..1
    const int wn = wid & 3;        // 0..3
    const int z = blockIdx.z;

    const __nv_bfloat16* __restrict__ Ahi = g_Xhi[z ? 1 : 0];
    const __nv_bfloat16* __restrict__ Alo = g_Xlo[z ? 1 : 0];
    const __nv_bfloat16* __restrict__ Bhi = g_Whi[z];
    const __nv_bfloat16* __restrict__ Blo = g_Wlo[z];
    float* __restrict__ Out = (z == 0) ? g_Q : (z == 1) ? g_K : g_V;

    const int m0 = blockIdx.y * 128;
    const int n0 = blockIdx.x * 128;

    const int lrow = tid >> 2;     // 0..63? no: tid/4 -> 0..63 ... need 128 rows over 2 its
    const int lq = tid & 3;

    float acc[4][4][4];
#pragma unroll
    for (int i = 0; i < 4; i++)
#pragma unroll
        for (int j = 0; j < 4; j++)
#pragma unroll
            for (int r = 0; r < 4; r++) acc[i][j][r] = 0.f;

    auto load_tile = [&](int kk, int stg) {
        const int pass = kk >> 5;
        const int k0 = (kk & 31) * 32;  // halves
        const __nv_bfloat16* A = (pass < 2) ? Ahi : Alo;
        const __nv_bfloat16* B = (pass == 1) ? Blo : Bhi;
#pragma unroll
        for (int it = 0; it < 2; it++) {
            int row = lrow + it * 64;
            const __nv_bfloat16* ga = A + (size_t)(m0 + row) * DIM + k0 + lq * 8;
            const __nv_bfloat16* gb = B + (size_t)(n0 + row) * DIM + k0 + lq * 8;
            cp16(smem_u32(&smA[stg][row][lq * 8]), ga);
            cp16(smem_u32(&smB[stg][row][lq * 8]), gb);
        }
    };

    load_tile(0, 0);
    CP_COMMIT();

    for (int kk = 0; kk < 96; kk++) {
        const int stg = kk & 1;
        if (kk + 1 < 96) {
            load_tile(kk + 1, stg ^ 1);
            CP_COMMIT();
            CP_WAIT1();
        } else {
            CP_WAIT0();
        }
        __syncthreads();

#pragma unroll
        for (int ks = 0; ks < 2; ks++) {
            const int kb = ks * 16;   // halves
            uint32_t a[4][4], b[4][2];
#pragma unroll
            for (int i = 0; i < 4; i++) {
                const int r0 = wm * 64 + i * 16;
                a[i][0] = *(const uint32_t*)&smA[stg][r0 + g][kb + tg * 2];
                a[i][1] = *(const uint32_t*)&smA[stg][r0 + 8 + g][kb + tg * 2];
                a[i][2] = *(const uint32_t*)&smA[stg][r0 + g][kb + 8 + tg * 2];
                a[i][3] = *(const uint32_t*)&smA[stg][r0 + 8 + g][kb + 8 + tg * 2];
            }
#pragma unroll
            for (int j = 0; j < 4; j++) {
                const int c0 = wn * 32 + j * 8;
                b[j][0] = *(const uint32_t*)&smB[stg][c0 + g][kb + tg * 2];
                b[j][1] = *(const uint32_t*)&smB[stg][c0 + g][kb + 8 + tg * 2];
            }
#pragma unroll
            for (int i = 0; i < 4; i++)
#pragma unroll
                for (int j = 0; j < 4; j++)
                    mma16816(acc[i][j], a[i], b[j]);
        }
        __syncthreads();
    }

    // epilogue: fp32 store (D frag: c0,c1 -> (row g, col tg*2); c2,c3 -> row g+8)
#pragma unroll
    for (int i = 0; i < 4; i++) {
        const int r0 = m0 + wm * 64 + i * 16 + g;
#pragma unroll
        for (int j = 0; j < 4; j++) {
            const int cc = n0 + wn * 32 + j * 8 + tg * 2;
            *(float2*)&Out[(size_t)r0 * DIM + cc] = make_float2(acc[i][j][0], acc[i][j][1]);
            *(float2*)&Out[(size_t)(r0 + 8) * DIM + cc] = make_float2(acc[i][j][2], acc[i][j][3]);
        }
    }
}

// ---------------- softmax over contiguous segments of 64 ----------------
__global__ __launch_bounds__(256)
void softmax64(int sel)
{
    float* buf = (sel == 0) ? g_Q : g_K;
    int seg = blockIdx.x * 8 + (threadIdx.x >> 5);
    int lane = threadIdx.x & 31;
    float* p = buf + (size_t)seg * 64;

    float v0 = p[lane];
    float v1 = p[lane + 32];
    float m = fmaxf(v0, v1);
#pragma unroll
    for (int o = 16; o > 0; o >>= 1) m = fmaxf(m, __shfl_xor_sync(0xffffffffu, m, o));
    float e0 = __expf(v0 - m);
    float e1 = __expf(v1 - m);
    float s = e0 + e1;
#pragma unroll
    for (int o = 16; o > 0; o >>= 1) s += __shfl_xor_sync(0xffffffffu, s, o);
    float inv = 1.0f / s;
    p[lane]      = e0 * inv;
    p[lane + 32] = e1 * inv;
}

// ---------------- per-chunk KV outer-product sums ----------------
__global__ __launch_bounds__(256)
void chunk_kv()
{
    extern __shared__ float sm[];
    float* ks = sm;          // 128*64
    float* vs = sm + 8192;   // 128*64

    const int c = blockIdx.x;
    const int nh = blockIdx.y;
    const int n = nh >> 4, h = nh & 15;
    const int t0 = c * CHK;
    const size_t base = ((size_t)(n * LSEQ + t0)) * DIM + h * DH;

    for (int idx = threadIdx.x; idx < CHK * DH; idx += 256) {
        int row = idx >> 6, col = idx & 63;
        ks[idx] = g_K[base + (size_t)row * DIM + col];
        vs[idx] = g_V[base + (size_t)row * DIM + col];
    }
    __syncthreads();

    const int tx = threadIdx.x & 15;
    const int ty = threadIdx.x >> 4;
    float acc[4][4];
#pragma unroll
    for (int i = 0; i < 4; i++)
#pragma unroll
        for (int j = 0; j < 4; j++) acc[i][j] = 0.f;

    for (int t = 0; t < CHK; t++) {
        float a[4], b[4];
#pragma unroll
        for (int i = 0; i < 4; i++) a[i] = ks[t * 64 + ty * 4 + i];
#pragma unroll
        for (int j = 0; j < 4; j++) b[j] = vs[t * 64 + tx * 4 + j];
#pragma unroll
        for (int i = 0; i < 4; i++)
#pragma unroll
            for (int j = 0; j < 4; j++)
                acc[i][j] = fmaf(a[i], b[j], acc[i][j]);
    }

    float* P = g_P + ((size_t)nh * NCHK + c) * (DH * DH);
#pragma unroll
    for (int i = 0; i < 4; i++)
#pragma unroll
        for (int j = 0; j < 4; j++)
            P[(ty * 4 + i) * 64 + tx * 4 + j] = acc[i][j];
}

// ---------------- exclusive prefix over chunks ----------------
__global__ __launch_bounds__(512)
void prefix_kv()
{
    float* P = g_P + (size_t)blockIdx.x * NCHK * (DH * DH);
    int e = threadIdx.x;
#pragma unroll
    for (int j = 0; j < 8; j++) {
        int idx = e + j * 512;
        float run = 0.f;
        for (int c = 0; c < NCHK; c++) {
            float t = P[c * (DH * DH) + idx];
            P[c * (DH * DH) + idx] = run;
            run += t;
        }
    }
}

// ---------------- attention output ----------------
__global__ __launch_bounds__(256)
void attn_out(float* __restrict__ out)
{
    extern __shared__ float sm[];
    float* qs = sm;            // 128*64
    float* Am = sm + 8192;     // 128*128
    float* R2 = sm + 24576;    // stage1: kT; stage2: vs + Ss

    const int c = blockIdx.x;
    const int nh = blockIdx.y;
    const int n = nh >> 4, h = nh & 15;
    const int t0 = c * CHK;
    const size_t base = ((size_t)(n * LSEQ + t0)) * DIM + h * DH;
    const int tid = threadIdx.x;
    const int tx = tid & 15;
    const int ty = tid >> 4;

    float* kT = R2;
    for (int idx = tid; idx < CHK * DH; idx += 256) {
        int row = idx >> 6, col = idx & 63;
        float qv = g_Q[base + (size_t)row * DIM + col];
        float kv = g_K[base + (size_t)row * DIM + col];
        qs[idx] = qv;
        kT[col * CHK + row] = kv;
    }
    __syncthreads();

    {
        float acc[8][8];
#pragma unroll
        for (int i = 0; i < 8; i++)
#pragma unroll
            for (int j = 0; j < 8; j++) acc[i][j] = 0.f;

        for (int d = 0; d < DH; d++) {
            float a[8], b[8];
#pragma unroll
            for (int i = 0; i < 8; i++) a[i] = qs[(ty * 8 + i) * 64 + d];
#pragma unroll
            for (int j = 0; j < 8; j++) b[j] = kT[d * CHK + tx * 8 + j];
#pragma unroll
            for (int i = 0; i < 8; i++)
#pragma unroll
                for (int j = 0; j < 8; j++)
                    acc[i][j] = fmaf(a[i], b[j], acc[i][j]);
        }
#pragma unroll
        for (int i = 0; i < 8; i++) {
            int r = ty * 8 + i;
#pragma unroll
            for (int j = 0; j < 8; j++) {
                int s = tx * 8 + j;
                Am[r * CHK + s] = (s <= r) ? acc[i][j] : 0.f;
            }
        }
    }
    __syncthreads();

    float* vs = R2;
    float* Ss = R2 + 8192;
    for (int idx = tid; idx < CHK * DH; idx += 256) {
        int row = idx >> 6, col = idx & 63;
        vs[idx] = g_V[base + (size_t)row * DIM + col];
    }
    {
        const float* Pp = g_P + ((size_t)nh * NCHK + c) * (DH * DH);
        for (int idx = tid; idx < DH * DH; idx += 256) Ss[idx] = Pp[idx];
    }
    __syncthreads();

    float o[8][4];
#pragma unroll
    for (int i = 0; i < 8; i++)
#pragma unroll
        for (int j = 0; j < 4; j++) o[i][j] = 0.f;

    for (int d = 0; d < DH; d++) {
        float a[8], b[4];
#pragma unroll
        for (int i = 0; i < 8; i++) a[i] = qs[(ty * 8 + i) * 64 + d];
#pragma unroll
        for (int j = 0; j < 4; j++) b[j] = Ss[d * 64 + tx * 4 + j];
#pragma unroll
        for (int i = 0; i < 8; i++)
#pragma unroll
            for (int j = 0; j < 4; j++)
                o[i][j] = fmaf(a[i], b[j], o[i][j]);
    }
    for (int s = 0; s < CHK; s++) {
        float a[8], b[4];
#pragma unroll
        for (int i = 0; i < 8; i++) a[i] = Am[(ty * 8 + i) * CHK + s];
#pragma unroll
        for (int j = 0; j < 4; j++) b[j] = vs[s * 64 + tx * 4 + j];
#pragma unroll
        for (int i = 0; i < 8; i++)
#pragma unroll
            for (int j = 0; j < 4; j++)
                o[i][j] = fmaf(a[i], b[j], o[i][j]);
    }

#pragma unroll
    for (int i = 0; i < 8; i++) {
        int r = ty * 8 + i;
#pragma unroll
        for (int j = 0; j < 4; j++)
            out[base + (size_t)r * DIM + tx * 4 + j] = o[i][j];
    }
}

// ---------------------------------------------------------------------------
extern "C" void kernel_launch(void* const* d_in, const int* in_sizes, int n_in,
                              void* d_out, int out_size)
{
    const float* query = (const float*)d_in[0];
    const float* key   = (const float*)d_in[1];
    const float* Wq    = (const float*)d_in[2];
    const float* Wk    = (const float*)d_in[3];
    const float* Wv    = (const float*)d_in[4];
    float* out = (float*)d_out;

    cudaFuncSetAttribute(chunk_kv, cudaFuncAttributeMaxDynamicSharedMemorySize, 65536);
    cudaFuncSetAttribute(attn_out, cudaFuncAttributeMaxDynamicSharedMemorySize, 147456);

    // 1. split fp32 -> bf16 hi/lo
    conv_split<<<dim3(128, 5), 256>>>(query, key, Wq, Wk, Wv);

    // 2. three projections on HMMA tensor cores (z: 0=Q,1=K,2=V)
    proj_hmma<<<dim3(8, 32, 3), 256>>>();

    // 3. per-head softmax for Q and K
    int nseg = MROWS * NH;
    softmax64<<<nseg / 8, 256>>>(0);
    softmax64<<<nseg / 8, 256>>>(1);

    // 4. chunked causal linear attention
    dim3 agrid(NCHK, NBATCH * NH);
    chunk_kv<<<agrid, 256, 65536>>>();
    prefix_kv<<<NBATCH * NH, 512>>>();
    attn_out<<<agrid, 256, 147456>>>(out);
}

// round 5
// speedup vs baseline: 1.8369x; 1.0743x over previous
#include <cuda_runtime.h>
#include <cuda_bf16.h>
#include <cstdint>
#include <cstddef>

// ---------------- problem constants ----------------
#define NBATCH 2
#define LSEQ   2048
#define DIM    1024
#define NH     16
#define DH     64
#define CHK    128
#define NCHK   (LSEQ / CHK)      // 16
#define MROWS  (NBATCH * LSEQ)   // 4096

// ---------------- device scratch (no allocs allowed) ----------------
__device__ __align__(16) float g_Q[MROWS * DIM];
__device__ __align__(16) float g_K[MROWS * DIM];
__device__ __align__(16) float g_V[MROWS * DIM];
__device__ __align__(16) float g_P[NBATCH * NH * NCHK * DH * DH];
__device__ __align__(16) __nv_bfloat16 g_Xhi[2][MROWS * DIM];   // 0=query 1=key
__device__ __align__(16) __nv_bfloat16 g_Xlo[2][MROWS * DIM];
__device__ __align__(16) __nv_bfloat16 g_Whi[3][DIM * DIM];     // Wq,Wk,Wv
__device__ __align__(16) __nv_bfloat16 g_Wlo[3][DIM * DIM];

// ---------------- small helpers ----------------
__device__ __forceinline__ uint32_t smem_u32(const void* p) {
    uint32_t a;
    asm("{ .reg .u64 t; cvta.to.shared.u64 t, %1; cvt.u32.u64 %0, t; }" : "=r"(a) : "l"(p));
    return a;
}
__device__ __forceinline__ void cp16(uint32_t s, const void* g) {
    asm volatile("cp.async.cg.shared.global [%0], [%1], 16;" :: "r"(s), "l"(g));
}
#define CP_COMMIT() asm volatile("cp.async.commit_group;" ::: "memory")
#define CP_WAIT1()  asm volatile("cp.async.wait_group 1;" ::: "memory")
#define CP_WAIT0()  asm volatile("cp.async.wait_group 0;" ::: "memory")

__device__ __forceinline__ void mma16816(float* c, const uint32_t* a, const uint32_t* b) {
    asm volatile(
        "mma.sync.aligned.m16n8k16.row.col.f32.bf16.bf16.f32 "
        "{%0,%1,%2,%3}, {%4,%5,%6,%7}, {%8,%9}, {%0,%1,%2,%3};"
        : "+f"(c[0]), "+f"(c[1]), "+f"(c[2]), "+f"(c[3])
        : "r"(a[0]), "r"(a[1]), "r"(a[2]), "r"(a[3]), "r"(b[0]), "r"(b[1]));
}
__device__ __forceinline__ void ldsm4(uint32_t* r, uint32_t addr) {
    asm volatile("ldmatrix.sync.aligned.m8n8.x4.shared.b16 {%0,%1,%2,%3}, [%4];"
                 : "=r"(r[0]), "=r"(r[1]), "=r"(r[2]), "=r"(r[3]) : "r"(addr));
}

// ---------------- bf16 hi/lo split conversion ----------------
__global__ __launch_bounds__(256)
void conv_split(const float* __restrict__ q, const float* __restrict__ k,
                const float* __restrict__ wq, const float* __restrict__ wk,
                const float* __restrict__ wv)
{
    int y = blockIdx.y;
    const float* src;
    __nv_bfloat16 *hi, *lo;
    int n;
    switch (y) {
        case 0: src = q;  hi = g_Xhi[0]; lo = g_Xlo[0]; n = MROWS * DIM; break;
        case 1: src = k;  hi = g_Xhi[1]; lo = g_Xlo[1]; n = MROWS * DIM; break;
        case 2: src = wq; hi = g_Whi[0]; lo = g_Wlo[0]; n = DIM * DIM;   break;
        case 3: src = wk; hi = g_Whi[1]; lo = g_Wlo[1]; n = DIM * DIM;   break;
        default: src = wv; hi = g_Whi[2]; lo = g_Wlo[2]; n = DIM * DIM;  break;
    }
    int n4 = n >> 2;
    for (int i = blockIdx.x * blockDim.x + threadIdx.x; i < n4;
         i += gridDim.x * blockDim.x) {
        float4 f = ((const float4*)src)[i];
        __nv_bfloat16 h0 = __float2bfloat16(f.x);
        __nv_bfloat16 h1 = __float2bfloat16(f.y);
        __nv_bfloat16 h2 = __float2bfloat16(f.z);
        __nv_bfloat16 h3 = __float2bfloat16(f.w);
        __nv_bfloat16 l0 = __float2bfloat16(f.x - __bfloat162float(h0));
        __nv_bfloat16 l1 = __float2bfloat16(f.y - __bfloat162float(h1));
        __nv_bfloat16 l2 = __float2bfloat16(f.z - __bfloat162float(h2));
        __nv_bfloat16 l3 = __float2bfloat16(f.w - __bfloat162float(h3));
        ushort4 uh = make_ushort4(__bfloat16_as_ushort(h0), __bfloat16_as_ushort(h1),
                                  __bfloat16_as_ushort(h2), __bfloat16_as_ushort(h3));
        ushort4 ul = make_ushort4(__bfloat16_as_ushort(l0), __bfloat16_as_ushort(l1),
                                  __bfloat16_as_ushort(l2), __bfloat16_as_ushort(l3));
        ((ushort4*)hi)[i] = uh;
        ((ushort4*)lo)[i] = ul;
    }
}

// ---------------- HMMA projection GEMM (ldmatrix + 3-stage pipeline) ----------------
// Out[m,n] = sum_k X[m,k]*W[n,k], as Ahi*Bhi + Ahi*Blo + Alo*Bhi.
// 128x128 CTA tile, BK=64 halves (48 iters = 3 passes x 16), 8 warps of 64x32,
// XOR-swizzled 128B rows, ldmatrix.x4 fragment loads, 3-stage cp.async ring.
#define STAGE_BYTES 32768                 // (A 16KB + B 16KB) per stage
#define SMEM_TOTAL  (3 * STAGE_BYTES)     // 96 KB

// swizzled byte offset of 16B chunk c (0..7) in row (128B pitch)
__device__ __forceinline__ uint32_t swz(int row, int c) {
    return (uint32_t)(row * 128 + ((c ^ (row & 7)) << 4));
}

__global__ __launch_bounds__(256, 2)
void proj_hmma()
{
    extern __shared__ char smem[];
    const uint32_t sb = smem_u32(smem);

    const int tid = threadIdx.x;
    const int wid = tid >> 5;
    const int lane = tid & 31;
    const int wm = wid >> 2;       // 0..1
    const int wn = wid & 3;        // 0..3
    const int z = blockIdx.z;

    const __nv_bfloat16* __restrict__ Ahi = g_Xhi[z ? 1 : 0];
    const __nv_bfloat16* __restrict__ Alo = g_Xlo[z ? 1 : 0];
    const __nv_bfloat16* __restrict__ Bhi = g_Whi[z];
    const __nv_bfloat16* __restrict__ Blo = g_Wlo[z];
    float* __restrict__ Out = (z == 0) ? g_Q : (z == 1) ? g_K : g_V;

    const int m0 = blockIdx.y * 128;
    const int n0 = blockIdx.x * 128;

    float acc[4][4][4];
#pragma unroll
    for (int i = 0; i < 4; i++)
#pragma unroll
        for (int j = 0; j < 4; j++)
#pragma unroll
            for (int r = 0; r < 4; r++) acc[i][j][r] = 0.f;

    // loader: kk in [0,48); pass = kk/16 selects hi/lo operands; k0 in halves
    const int lrow = tid >> 1;           // 0..127
    const int lc4  = (tid & 1) * 4;      // chunk 0 or 4
    auto load_tile = [&](int kk, int stg) {
        const int pass = kk >> 4;
        const int k0 = (kk & 15) * 64;
        const __nv_bfloat16* A = (pass < 2) ? Ahi : Alo;
        const __nv_bfloat16* B = (pass == 1) ? Blo : Bhi;
        const uint32_t sa = sb + stg * STAGE_BYTES;
        const uint32_t sbB = sa + 16384;
        const __nv_bfloat16* ga = A + (size_t)(m0 + lrow) * DIM + k0 + lc4 * 8;
        const __nv_bfloat16* gb = B + (size_t)(n0 + lrow) * DIM + k0 + lc4 * 8;
#pragma unroll
        for (int c = 0; c < 4; c++) {
            cp16(sa  + swz(lrow, lc4 + c), ga + c * 8);
            cp16(sbB + swz(lrow, lc4 + c), gb + c * 8);
        }
    };

    // fragment-load address components (per-lane, loop-invariant)
    const int a_row = (lane & 7) + ((lane >> 3) & 1) * 8;   // within 16-row frag
    const int a_cofs = lane >> 4;                           // 0..1 -> chunk offset
    const int b_row0 = ((lane >> 4) & 1) * 8 + (lane & 7);  // within 16-col pair
    const int b_cofs = (lane >> 3) & 1;

    load_tile(0, 0); CP_COMMIT();
    load_tile(1, 1); CP_COMMIT();

    for (int kk = 0; kk < 48; kk++) {
        const int stg = kk % 3;
        CP_WAIT1();
        __syncthreads();
        if (kk + 2 < 48) { load_tile(kk + 2, (kk + 2) % 3); CP_COMMIT(); }

        const uint32_t sa = sb + stg * STAGE_BYTES;
        const uint32_t sbB = sa + 16384;

#pragma unroll
        for (int ks = 0; ks < 4; ks++) {
            const int c0 = ks * 2;
            uint32_t a[4][4], b[8];
#pragma unroll
            for (int i = 0; i < 4; i++) {
                const int r0 = wm * 64 + i * 16;
                ldsm4(a[i], sa + swz(r0 + a_row, c0 + a_cofs));
            }
#pragma unroll
            for (int jp = 0; jp < 2; jp++) {
                const int c0b = wn * 32 + jp * 16;
                ldsm4(&b[jp * 4], sbB + swz(c0b + b_row0, c0 + b_cofs));
            }
#pragma unroll
            for (int i = 0; i < 4; i++)
#pragma unroll
                for (int j = 0; j < 4; j++)
                    mma16816(acc[i][j], a[i], &b[j * 2]);
        }
    }

    // epilogue: fp32 store (c0,c1 -> (row g, col tg*2); c2,c3 -> row g+8)
    const int g = lane >> 2;
    const int tg = lane & 3;
#pragma unroll
    for (int i = 0; i < 4; i++) {
        const int r0 = m0 + wm * 64 + i * 16 + g;
#pragma unroll
        for (int j = 0; j < 4; j++) {
            const int cc = n0 + wn * 32 + j * 8 + tg * 2;
            *(float2*)&Out[(size_t)r0 * DIM + cc] = make_float2(acc[i][j][0], acc[i][j][1]);
            *(float2*)&Out[(size_t)(r0 + 8) * DIM + cc] = make_float2(acc[i][j][2], acc[i][j][3]);
        }
    }
}

// ---------------- softmax over contiguous segments of 64 ----------------
__global__ __launch_bounds__(256)
void softmax64(int sel)
{
    float* buf = (sel == 0) ? g_Q : g_K;
    int seg = blockIdx.x * 8 + (threadIdx.x >> 5);
    int lane = threadIdx.x & 31;
    float* p = buf + (size_t)seg * 64;

    float v0 = p[lane];
    float v1 = p[lane + 32];
    float m = fmaxf(v0, v1);
#pragma unroll
    for (int o = 16; o > 0; o >>= 1) m = fmaxf(m, __shfl_xor_sync(0xffffffffu, m, o));
    float e0 = __expf(v0 - m);
    float e1 = __expf(v1 - m);
    float s = e0 + e1;
#pragma unroll
    for (int o = 16; o > 0; o >>= 1) s += __shfl_xor_sync(0xffffffffu, s, o);
    float inv = 1.0f / s;
    p[lane]      = e0 * inv;
    p[lane + 32] = e1 * inv;
}

// ---------------- per-chunk KV outer-product sums ----------------
__global__ __launch_bounds__(256)
void chunk_kv()
{
    extern __shared__ float sm[];
    float* ks = sm;          // 128*64
    float* vs = sm + 8192;   // 128*64

    const int c = blockIdx.x;
    const int nh = blockIdx.y;
    const int n = nh >> 4, h = nh & 15;
    const int t0 = c * CHK;
    const size_t base = ((size_t)(n * LSEQ + t0)) * DIM + h * DH;

    for (int idx = threadIdx.x; idx < CHK * DH; idx += 256) {
        int row = idx >> 6, col = idx & 63;
        ks[idx] = g_K[base + (size_t)row * DIM + col];
        vs[idx] = g_V[base + (size_t)row * DIM + col];
    }
    __syncthreads();

    const int tx = threadIdx.x & 15;
    const int ty = threadIdx.x >> 4;
    float acc[4][4];
#pragma unroll
    for (int i = 0; i < 4; i++)
#pragma unroll
        for (int j = 0; j < 4; j++) acc[i][j] = 0.f;

    for (int t = 0; t < CHK; t++) {
        float a[4], b[4];
#pragma unroll
        for (int i = 0; i < 4; i++) a[i] = ks[t * 64 + ty * 4 + i];
#pragma unroll
        for (int j = 0; j < 4; j++) b[j] = vs[t * 64 + tx * 4 + j];
#pragma unroll
        for (int i = 0; i < 4; i++)
#pragma unroll
            for (int j = 0; j < 4; j++)
                acc[i][j] = fmaf(a[i], b[j], acc[i][j]);
    }

    float* P = g_P + ((size_t)nh * NCHK + c) * (DH * DH);
#pragma unroll
    for (int i = 0; i < 4; i++)
#pragma unroll
        for (int j = 0; j < 4; j++)
            P[(ty * 4 + i) * 64 + tx * 4 + j] = acc[i][j];
}

// ---------------- exclusive prefix over chunks ----------------
__global__ __launch_bounds__(512)
void prefix_kv()
{
    float* P = g_P + (size_t)blockIdx.x * NCHK * (DH * DH);
    int e = threadIdx.x;
#pragma unroll
    for (int j = 0; j < 8; j++) {
        int idx = e + j * 512;
        float run = 0.f;
        for (int c = 0; c < NCHK; c++) {
            float t = P[c * (DH * DH) + idx];
            P[c * (DH * DH) + idx] = run;
            run += t;
        }
    }
}

// ---------------- attention output ----------------
__global__ __launch_bounds__(256)
void attn_out(float* __restrict__ out)
{
    extern __shared__ float sm[];
    float* qs = sm;            // 128*64
    float* Am = sm + 8192;     // 128*128
    float* R2 = sm + 24576;    // stage1: kT; stage2: vs + Ss

    const int c = blockIdx.x;
    const int nh = blockIdx.y;
    const int n = nh >> 4, h = nh & 15;
    const int t0 = c * CHK;
    const size_t base = ((size_t)(n * LSEQ + t0)) * DIM + h * DH;
    const int tid = threadIdx.x;
    const int tx = tid & 15;
    const int ty = tid >> 4;

    float* kT = R2;
    for (int idx = tid; idx < CHK * DH; idx += 256) {
        int row = idx >> 6, col = idx & 63;
        float qv = g_Q[base + (size_t)row * DIM + col];
        float kv = g_K[base + (size_t)row * DIM + col];
        qs[idx] = qv;
        kT[col * CHK + row] = kv;
    }
    __syncthreads();

    {
        float acc[8][8];
#pragma unroll
        for (int i = 0; i < 8; i++)
#pragma unroll
            for (int j = 0; j < 8; j++) acc[i][j] = 0.f;

        for (int d = 0; d < DH; d++) {
            float a[8], b[8];
#pragma unroll
            for (int i = 0; i < 8; i++) a[i] = qs[(ty * 8 + i) * 64 + d];
#pragma unroll
            for (int j = 0; j < 8; j++) b[j] = kT[d * CHK + tx * 8 + j];
#pragma unroll
            for (int i = 0; i < 8; i++)
#pragma unroll
                for (int j = 0; j < 8; j++)
                    acc[i][j] = fmaf(a[i], b[j], acc[i][j]);
        }
#pragma unroll
        for (int i = 0; i < 8; i++) {
            int r = ty * 8 + i;
#pragma unroll
            for (int j = 0; j < 8; j++) {
                int s = tx * 8 + j;
                Am[r * CHK + s] = (s <= r) ? acc[i][j] : 0.f;
            }
        }
    }
    __syncthreads();

    float* vs = R2;
    float* Ss = R2 + 8192;
    for (int idx = tid; idx < CHK * DH; idx += 256) {
        int row = idx >> 6, col = idx & 63;
        vs[idx] = g_V[base + (size_t)row * DIM + col];
    }
    {
        const float* Pp = g_P + ((size_t)nh * NCHK + c) * (DH * DH);
        for (int idx = tid; idx < DH * DH; idx += 256) Ss[idx] = Pp[idx];
    }
    __syncthreads();

    float o[8][4];
#pragma unroll
    for (int i = 0; i < 8; i++)
#pragma unroll
        for (int j = 0; j < 4; j++) o[i][j] = 0.f;

    for (int d = 0; d < DH; d++) {
        float a[8], b[4];
#pragma unroll
        for (int i = 0; i < 8; i++) a[i] = qs[(ty * 8 + i) * 64 + d];
#pragma unroll
        for (int j = 0; j < 4; j++) b[j] = Ss[d * 64 + tx * 4 + j];
#pragma unroll
        for (int i = 0; i < 8; i++)
#pragma unroll
            for (int j = 0; j < 4; j++)
                o[i][j] = fmaf(a[i], b[j], o[i][j]);
    }
    for (int s = 0; s < CHK; s++) {
        float a[8], b[4];
#pragma unroll
        for (int i = 0; i < 8; i++) a[i] = Am[(ty * 8 + i) * CHK + s];
#pragma unroll
        for (int j = 0; j < 4; j++) b[j] = vs[s * 64 + tx * 4 + j];
#pragma unroll
        for (int i = 0; i < 8; i++)
#pragma unroll
            for (int j = 0; j < 4; j++)
                o[i][j] = fmaf(a[i], b[j], o[i][j]);
    }

#pragma unroll
    for (int i = 0; i < 8; i++) {
        int r = ty * 8 + i;
#pragma unroll
        for (int j = 0; j < 4; j++)
            out[base + (size_t)r * DIM + tx * 4 + j] = o[i][j];
    }
}

// ---------------------------------------------------------------------------
extern "C" void kernel_launch(void* const* d_in, const int* in_sizes, int n_in,
                              void* d_out, int out_size)
{
    const float* query = (const float*)d_in[0];
    const float* key   = (const float*)d_in[1];
    const float* Wq    = (const float*)d_in[2];
    const float* Wk    = (const float*)d_in[3];
    const float* Wv    = (const float*)d_in[4];
    float* out = (float*)d_out;

    cudaFuncSetAttribute(proj_hmma, cudaFuncAttributeMaxDynamicSharedMemorySize, SMEM_TOTAL);
    cudaFuncSetAttribute(chunk_kv, cudaFuncAttributeMaxDynamicSharedMemorySize, 65536);
    cudaFuncSetAttribute(attn_out, cudaFuncAttributeMaxDynamicSharedMemorySize, 147456);

    // 1. split fp32 -> bf16 hi/lo
    conv_split<<<dim3(128, 5), 256>>>(query, key, Wq, Wk, Wv);

    // 2. three projections on HMMA tensor cores (z: 0=Q,1=K,2=V)
    proj_hmma<<<dim3(8, 32, 3), 256, SMEM_TOTAL>>>();

    // 3. per-head softmax for Q and K
    int nseg = MROWS * NH;
    softmax64<<<nseg / 8, 256>>>(0);
    softmax64<<<nseg / 8, 256>>>(1);

    // 4. chunked causal linear attention
    dim3 agrid(NCHK, NBATCH * NH);
    chunk_kv<<<agrid, 256, 65536>>>();
    prefix_kv<<<NBATCH * NH, 512>>>();
    attn_out<<<agrid, 256, 147456>>>(out);
}

// round 6
// speedup vs baseline: 1.9613x; 1.0677x over previous
#include <cuda_runtime.h>
#include <cuda_bf16.h>
#include <cstdint>
#include <cstddef>

// ---------------- problem constants ----------------
#define NBATCH 2
#define LSEQ   2048
#define DIM    1024
#define NH     16
#define DH     64
#define CHK    128
#define NCHK   (LSEQ / CHK)      // 16
#define MROWS  (NBATCH * LSEQ)   // 4096

// ---------------- device scratch (no allocs allowed) ----------------
__device__ __align__(16) float g_Q[MROWS * DIM];
__device__ __align__(16) float g_K[MROWS * DIM];
__device__ __align__(16) float g_V[MROWS * DIM];
__device__ __align__(16) float g_P[NBATCH * NH * NCHK * DH * DH];
__device__ __align__(16) __nv_bfloat16 g_Xhi[2][MROWS * DIM];   // 0=query 1=key
__device__ __align__(16) __nv_bfloat16 g_Xlo[2][MROWS * DIM];
__device__ __align__(16) __nv_bfloat16 g_Whi[3][DIM * DIM];     // Wq,Wk,Wv
__device__ __align__(16) __nv_bfloat16 g_Wlo[3][DIM * DIM];

// ---------------- small helpers ----------------
__device__ __forceinline__ uint32_t smem_u32(const void* p) {
    uint32_t a;
    asm("{ .reg .u64 t; cvta.to.shared.u64 t, %1; cvt.u32.u64 %0, t; }" : "=r"(a) : "l"(p));
    return a;
}
__device__ __forceinline__ void cp16(uint32_t s, const void* g) {
    asm volatile("cp.async.cg.shared.global [%0], [%1], 16;" :: "r"(s), "l"(g));
}
#define CP_COMMIT() asm volatile("cp.async.commit_group;" ::: "memory")
#define CP_WAIT1()  asm volatile("cp.async.wait_group 1;" ::: "memory")

__device__ __forceinline__ void mma16816(float* c, const uint32_t* a, const uint32_t* b) {
    asm volatile(
        "mma.sync.aligned.m16n8k16.row.col.f32.bf16.bf16.f32 "
        "{%0,%1,%2,%3}, {%4,%5,%6,%7}, {%8,%9}, {%0,%1,%2,%3};"
        : "+f"(c[0]), "+f"(c[1]), "+f"(c[2]), "+f"(c[3])
        : "r"(a[0]), "r"(a[1]), "r"(a[2]), "r"(a[3]), "r"(b[0]), "r"(b[1]));
}
__device__ __forceinline__ void ldsm4(uint32_t* r, uint32_t addr) {
    asm volatile("ldmatrix.sync.aligned.m8n8.x4.shared.b16 {%0,%1,%2,%3}, [%4];"
                 : "=r"(r[0]), "=r"(r[1]), "=r"(r[2]), "=r"(r[3]) : "r"(addr));
}

// ---------------- bf16 hi/lo split conversion ----------------
__global__ __launch_bounds__(256)
void conv_split(const float* __restrict__ q, const float* __restrict__ k,
                const float* __restrict__ wq, const float* __restrict__ wk,
                const float* __restrict__ wv)
{
    int y = blockIdx.y;
    const float* src;
    __nv_bfloat16 *hi, *lo;
    int n;
    switch (y) {
        case 0: src = q;  hi = g_Xhi[0]; lo = g_Xlo[0]; n = MROWS * DIM; break;
        case 1: src = k;  hi = g_Xhi[1]; lo = g_Xlo[1]; n = MROWS * DIM; break;
        case 2: src = wq; hi = g_Whi[0]; lo = g_Wlo[0]; n = DIM * DIM;   break;
        case 3: src = wk; hi = g_Whi[1]; lo = g_Wlo[1]; n = DIM * DIM;   break;
        default: src = wv; hi = g_Whi[2]; lo = g_Wlo[2]; n = DIM * DIM;  break;
    }
    int n4 = n >> 2;
    for (int i = blockIdx.x * blockDim.x + threadIdx.x; i < n4;
         i += gridDim.x * blockDim.x) {
        float4 f = ((const float4*)src)[i];
        __nv_bfloat16 h0 = __float2bfloat16(f.x);
        __nv_bfloat16 h1 = __float2bfloat16(f.y);
        __nv_bfloat16 h2 = __float2bfloat16(f.z);
        __nv_bfloat16 h3 = __float2bfloat16(f.w);
        __nv_bfloat16 l0 = __float2bfloat16(f.x - __bfloat162float(h0));
        __nv_bfloat16 l1 = __float2bfloat16(f.y - __bfloat162float(h1));
        __nv_bfloat16 l2 = __float2bfloat16(f.z - __bfloat162float(h2));
        __nv_bfloat16 l3 = __float2bfloat16(f.w - __bfloat162float(h3));
        ushort4 uh = make_ushort4(__bfloat16_as_ushort(h0), __bfloat16_as_ushort(h1),
                                  __bfloat16_as_ushort(h2), __bfloat16_as_ushort(h3));
        ushort4 ul = make_ushort4(__bfloat16_as_ushort(l0), __bfloat16_as_ushort(l1),
                                  __bfloat16_as_ushort(l2), __bfloat16_as_ushort(l3));
        ((ushort4*)hi)[i] = uh;
        ((ushort4*)lo)[i] = ul;
    }
}

// ---------------- HMMA projection GEMM (+ fused per-head softmax) ----------------
// Out[m,n] = sum_k X[m,k]*W[n,k], as Ahi*Bhi + Ahi*Blo + Alo*Bhi.
// 128x128 CTA tile, BK=64 halves (48 iters), 8 warps of 64x32, ldmatrix.x4,
// XOR-swizzled 128B rows, 3-stage cp.async ring.
// Epilogue (z<2): softmax over each 64-col head segment, then fp32 store.
#define STAGE_BYTES 32768
#define SMEM_TOTAL  (3 * STAGE_BYTES)     // 96 KB

__device__ __forceinline__ uint32_t swz(int row, int c) {
    return (uint32_t)(row * 128 + ((c ^ (row & 7)) << 4));
}

__global__ __launch_bounds__(256, 2)
void proj_hmma()
{
    extern __shared__ char smem[];
    const uint32_t sb = smem_u32(smem);

    const int tid = threadIdx.x;
    const int wid = tid >> 5;
    const int lane = tid & 31;
    const int wm = wid >> 2;       // 0..1
    const int wn = wid & 3;        // 0..3
    const int z = blockIdx.z;

    const __nv_bfloat16* __restrict__ Ahi = g_Xhi[z ? 1 : 0];
    const __nv_bfloat16* __restrict__ Alo = g_Xlo[z ? 1 : 0];
    const __nv_bfloat16* __restrict__ Bhi = g_Whi[z];
    const __nv_bfloat16* __restrict__ Blo = g_Wlo[z];
    float* __restrict__ Out = (z == 0) ? g_Q : (z == 1) ? g_K : g_V;

    const int m0 = blockIdx.y * 128;
    const int n0 = blockIdx.x * 128;

    float acc[4][4][4];
#pragma unroll
    for (int i = 0; i < 4; i++)
#pragma unroll
        for (int j = 0; j < 4; j++)
#pragma unroll
            for (int r = 0; r < 4; r++) acc[i][j][r] = 0.f;

    const int lrow = tid >> 1;
    const int lc4  = (tid & 1) * 4;
    auto load_tile = [&](int kk, int stg) {
        const int pass = kk >> 4;
        const int k0 = (kk & 15) * 64;
        const __nv_bfloat16* A = (pass < 2) ? Ahi : Alo;
        const __nv_bfloat16* B = (pass == 1) ? Blo : Bhi;
        const uint32_t sa = sb + stg * STAGE_BYTES;
        const uint32_t sbB = sa + 16384;
        const __nv_bfloat16* ga = A + (size_t)(m0 + lrow) * DIM + k0 + lc4 * 8;
        const __nv_bfloat16* gb = B + (size_t)(n0 + lrow) * DIM + k0 + lc4 * 8;
#pragma unroll
        for (int c = 0; c < 4; c++) {
            cp16(sa  + swz(lrow, lc4 + c), ga + c * 8);
            cp16(sbB + swz(lrow, lc4 + c), gb + c * 8);
        }
    };

    const int a_row = (lane & 7) + ((lane >> 3) & 1) * 8;
    const int a_cofs = lane >> 4;
    const int b_row0 = ((lane >> 4) & 1) * 8 + (lane & 7);
    const int b_cofs = (lane >> 3) & 1;

    load_tile(0, 0); CP_COMMIT();
    load_tile(1, 1); CP_COMMIT();

    for (int kk = 0; kk < 48; kk++) {
        const int stg = kk % 3;
        CP_WAIT1();
        __syncthreads();
        if (kk + 2 < 48) { load_tile(kk + 2, (kk + 2) % 3); CP_COMMIT(); }

        const uint32_t sa = sb + stg * STAGE_BYTES;
        const uint32_t sbB = sa + 16384;

#pragma unroll
        for (int ks = 0; ks < 4; ks++) {
            const int c0 = ks * 2;
            uint32_t a[4][4], b[8];
#pragma unroll
            for (int i = 0; i < 4; i++) {
                const int r0 = wm * 64 + i * 16;
                ldsm4(a[i], sa + swz(r0 + a_row, c0 + a_cofs));
            }
#pragma unroll
            for (int jp = 0; jp < 2; jp++) {
                const int c0b = wn * 32 + jp * 16;
                ldsm4(&b[jp * 4], sbB + swz(c0b + b_row0, c0 + b_cofs));
            }
#pragma unroll
            for (int i = 0; i < 4; i++)
#pragma unroll
                for (int j = 0; j < 4; j++)
                    mma16816(acc[i][j], a[i], &b[j * 2]);
        }
    }

    // ---------------- epilogue ----------------
    const int g = lane >> 2;
    const int tg = lane & 3;
    __syncthreads();   // main-loop smem no longer needed

    if (z < 2) {
        // per-head softmax over 64-col segments. seg = wn>>1; warp pair (wn&1).
        float* red = (float*)smem;   // [128 rows][2 seg][2 pair] = 512 floats
        const int seg = wn >> 1;
        const int pr = wn & 1;

        // 1) local max over this thread's 8 cols per (i, half)
        float ml[4][2];
#pragma unroll
        for (int i = 0; i < 4; i++)
#pragma unroll
            for (int h = 0; h < 2; h++) {
                float m = acc[i][0][h * 2];
#pragma unroll
                for (int j = 0; j < 4; j++) {
                    m = fmaxf(m, acc[i][j][h * 2]);
                    m = fmaxf(m, acc[i][j][h * 2 + 1]);
                }
                // reduce over tg (lane bits 0,1)
                m = fmaxf(m, __shfl_xor_sync(0xffffffffu, m, 1));
                m = fmaxf(m, __shfl_xor_sync(0xffffffffu, m, 2));
                ml[i][h] = m;
            }
        if (tg == 0) {
#pragma unroll
            for (int i = 0; i < 4; i++)
#pragma unroll
                for (int h = 0; h < 2; h++) {
                    int row = wm * 64 + i * 16 + h * 8 + g;
                    red[(row * 2 + seg) * 2 + pr] = ml[i][h];
                }
        }
        __syncthreads();
        float mseg[4][2];
#pragma unroll
        for (int i = 0; i < 4; i++)
#pragma unroll
            for (int h = 0; h < 2; h++) {
                int row = wm * 64 + i * 16 + h * 8 + g;
                mseg[i][h] = fmaxf(red[(row * 2 + seg) * 2 + 0],
                                   red[(row * 2 + seg) * 2 + 1]);
            }
        __syncthreads();   // before reusing red for sums

        // 2) exp + local sum
        float sl[4][2];
#pragma unroll
        for (int i = 0; i < 4; i++)
#pragma unroll
            for (int h = 0; h < 2; h++) {
                float s = 0.f;
#pragma unroll
                for (int j = 0; j < 4; j++) {
                    float e0 = __expf(acc[i][j][h * 2]     - mseg[i][h]);
                    float e1 = __expf(acc[i][j][h * 2 + 1] - mseg[i][h]);
                    acc[i][j][h * 2] = e0; acc[i][j][h * 2 + 1] = e1;
                    s += e0 + e1;
                }
                s += __shfl_xor_sync(0xffffffffu, s, 1);
                s += __shfl_xor_sync(0xffffffffu, s, 2);
                sl[i][h] = s;
            }
        if (tg == 0) {
#pragma unroll
            for (int i = 0; i < 4; i++)
#pragma unroll
                for (int h = 0; h < 2; h++) {
                    int row = wm * 64 + i * 16 + h * 8 + g;
                    red[(row * 2 + seg) * 2 + pr] = sl[i][h];
                }
        }
        __syncthreads();
#pragma unroll
        for (int i = 0; i < 4; i++)
#pragma unroll
            for (int h = 0; h < 2; h++) {
                int row = wm * 64 + i * 16 + h * 8 + g;
                float inv = 1.0f / (red[(row * 2 + seg) * 2 + 0] +
                                    red[(row * 2 + seg) * 2 + 1]);
#pragma unroll
                for (int j = 0; j < 4; j++) {
                    acc[i][j][h * 2]     *= inv;
                    acc[i][j][h * 2 + 1] *= inv;
                }
            }
    }

    // store fp32
#pragma unroll
    for (int i = 0; i < 4; i++) {
        const int r0 = m0 + wm * 64 + i * 16 + g;
#pragma unroll
        for (int j = 0; j < 4; j++) {
            const int cc = n0 + wn * 32 + j * 8 + tg * 2;
            *(float2*)&Out[(size_t)r0 * DIM + cc] = make_float2(acc[i][j][0], acc[i][j][1]);
            *(float2*)&Out[(size_t)(r0 + 8) * DIM + cc] = make_float2(acc[i][j][2], acc[i][j][3]);
        }
    }
}

// ---------------- per-chunk KV outer-product sums ----------------
__global__ __launch_bounds__(256)
void chunk_kv()
{
    extern __shared__ float sm[];
    float* ks = sm;          // 128*64
    float* vs = sm + 8192;   // 128*64

    const int c = blockIdx.x;
    const int nh = blockIdx.y;
    const int n = nh >> 4, h = nh & 15;
    const int t0 = c * CHK;
    const size_t base = ((size_t)(n * LSEQ + t0)) * DIM + h * DH;

    for (int idx = threadIdx.x; idx < CHK * DH; idx += 256) {
        int row = idx >> 6, col = idx & 63;
        ks[idx] = g_K[base + (size_t)row * DIM + col];
        vs[idx] = g_V[base + (size_t)row * DIM + col];
    }
    __syncthreads();

    const int tx = threadIdx.x & 15;
    const int ty = threadIdx.x >> 4;
    float acc[4][4];
#pragma unroll
    for (int i = 0; i < 4; i++)
#pragma unroll
        for (int j = 0; j < 4; j++) acc[i][j] = 0.f;

    for (int t = 0; t < CHK; t++) {
        float a[4], b[4];
#pragma unroll
        for (int i = 0; i < 4; i++) a[i] = ks[t * 64 + ty * 4 + i];
#pragma unroll
        for (int j = 0; j < 4; j++) b[j] = vs[t * 64 + tx * 4 + j];
#pragma unroll
        for (int i = 0; i < 4; i++)
#pragma unroll
            for (int j = 0; j < 4; j++)
                acc[i][j] = fmaf(a[i], b[j], acc[i][j]);
    }

    float* P = g_P + ((size_t)nh * NCHK + c) * (DH * DH);
#pragma unroll
    for (int i = 0; i < 4; i++)
#pragma unroll
        for (int j = 0; j < 4; j++)
            P[(ty * 4 + i) * 64 + tx * 4 + j] = acc[i][j];
}

// ---------------- exclusive prefix over chunks ----------------
// grid: NB*NH*8 blocks of 512; one element-slice per thread (coalesced).
__global__ __launch_bounds__(512)
void prefix_kv()
{
    const int nh = blockIdx.x >> 3;
    const int slab = blockIdx.x & 7;
    float* P = g_P + (size_t)nh * NCHK * (DH * DH);
    const int idx = slab * 512 + threadIdx.x;
    float run = 0.f;
#pragma unroll
    for (int c = 0; c < NCHK; c++) {
        float t = P[c * (DH * DH) + idx];
        P[c * (DH * DH) + idx] = run;
        run += t;
    }
}

// ---------------- attention output ----------------
__global__ __launch_bounds__(256)
void attn_out(float* __restrict__ out)
{
    extern __shared__ float sm[];
    float* qs = sm;            // 128*64
    float* Am = sm + 8192;     // 128*128
    float* R2 = sm + 24576;    // stage1: kT; stage2: vs + Ss

    const int c = blockIdx.x;
    const int nh = blockIdx.y;
    const int n = nh >> 4, h = nh & 15;
    const int t0 = c * CHK;
    const size_t base = ((size_t)(n * LSEQ + t0)) * DIM + h * DH;
    const int tid = threadIdx.x;
    const int tx = tid & 15;
    const int ty = tid >> 4;

    float* kT = R2;
    for (int idx = tid; idx < CHK * DH; idx += 256) {
        int row = idx >> 6, col = idx & 63;
        float qv = g_Q[base + (size_t)row * DIM + col];
        float kv = g_K[base + (size_t)row * DIM + col];
        qs[idx] = qv;
        kT[col * CHK + row] = kv;
    }
    __syncthreads();

    {
        float acc[8][8];
#pragma unroll
        for (int i = 0; i < 8; i++)
#pragma unroll
            for (int j = 0; j < 8; j++) acc[i][j] = 0.f;

        for (int d = 0; d < DH; d++) {
            float a[8], b[8];
#pragma unroll
            for (int i = 0; i < 8; i++) a[i] = qs[(ty * 8 + i) * 64 + d];
#pragma unroll
            for (int j = 0; j < 8; j++) b[j] = kT[d * CHK + tx * 8 + j];
#pragma unroll
            for (int i = 0; i < 8; i++)
#pragma unroll
                for (int j = 0; j < 8; j++)
                    acc[i][j] = fmaf(a[i], b[j], acc[i][j]);
        }
#pragma unroll
        for (int i = 0; i < 8; i++) {
            int r = ty * 8 + i;
#pragma unroll
            for (int j = 0; j < 8; j++) {
                int s = tx * 8 + j;
                Am[r * CHK + s] = (s <= r) ? acc[i][j] : 0.f;
            }
        }
    }
    __syncthreads();

    float* vs = R2;
    float* Ss = R2 + 8192;
    for (int idx = tid; idx < CHK * DH; idx += 256) {
        int row = idx >> 6, col = idx & 63;
        vs[idx] = g_V[base + (size_t)row * DIM + col];
    }
    {
        const float* Pp = g_P + ((size_t)nh * NCHK + c) * (DH * DH);
        for (int idx = tid; idx < DH * DH; idx += 256) Ss[idx] = Pp[idx];
    }
    __syncthreads();

    float o[8][4];
#pragma unroll
    for (int i = 0; i < 8; i++)
#pragma unroll
        for (int j = 0; j < 4; j++) o[i][j] = 0.f;

    for (int d = 0; d < DH; d++) {
        float a[8], b[4];
#pragma unroll
        for (int i = 0; i < 8; i++) a[i] = qs[(ty * 8 + i) * 64 + d];
#pragma unroll
        for (int j = 0; j < 4; j++) b[j] = Ss[d * 64 + tx * 4 + j];
#pragma unroll
        for (int i = 0; i < 8; i++)
#pragma unroll
            for (int j = 0; j < 4; j++)
                o[i][j] = fmaf(a[i], b[j], o[i][j]);
    }
    // causal: A[r][s] = 0 for s > r; warp rows reach 16*warp+15 -> bound s.
    const int sHi = ((tid >> 5) + 1) * 16;
    for (int s = 0; s < sHi; s++) {
        float a[8], b[4];
#pragma unroll
        for (int i = 0; i < 8; i++) a[i] = Am[(ty * 8 + i) * CHK + s];
#pragma unroll
        for (int j = 0; j < 4; j++) b[j] = vs[s * 64 + tx * 4 + j];
#pragma unroll
        for (int i = 0; i < 8; i++)
#pragma unroll
            for (int j = 0; j < 4; j++)
                o[i][j] = fmaf(a[i], b[j], o[i][j]);
    }

#pragma unroll
    for (int i = 0; i < 8; i++) {
        int r = ty * 8 + i;
#pragma unroll
        for (int j = 0; j < 4; j++)
            out[base + (size_t)r * DIM + tx * 4 + j] = o[i][j];
    }
}

// ---------------------------------------------------------------------------
extern "C" void kernel_launch(void* const* d_in, const int* in_sizes, int n_in,
                              void* d_out, int out_size)
{
    const float* query = (const float*)d_in[0];
    const float* key   = (const float*)d_in[1];
    const float* Wq    = (const float*)d_in[2];
    const float* Wk    = (const float*)d_in[3];
    const float* Wv    = (const float*)d_in[4];
    float* out = (float*)d_out;

    cudaFuncSetAttribute(proj_hmma, cudaFuncAttributeMaxDynamicSharedMemorySize, SMEM_TOTAL);
    cudaFuncSetAttribute(chunk_kv, cudaFuncAttributeMaxDynamicSharedMemorySize, 65536);
    cudaFuncSetAttribute(attn_out, cudaFuncAttributeMaxDynamicSharedMemorySize, 147456);

    // 1. split fp32 -> bf16 hi/lo
    conv_split<<<dim3(128, 5), 256>>>(query, key, Wq, Wk, Wv);

    // 2. projections on HMMA (z: 0=Q,1=K,2=V) with fused per-head softmax
    proj_hmma<<<dim3(8, 32, 3), 256, SMEM_TOTAL>>>();

    // 3. chunked causal linear attention
    dim3 agrid(NCHK, NBATCH * NH);
    chunk_kv<<<agrid, 256, 65536>>>();
    prefix_kv<<<NBATCH * NH * 8, 512>>>();
    attn_out<<<agrid, 256, 147456>>>(out);
}